// round 10
// baseline (speedup 1.0000x reference)
#include <cuda_runtime.h>
#include <math.h>

// PINN beam fields: Taylor-jet table (129 nodes) + nearest-node Taylor eval.
// build_tab: 16 lanes per node (one layer-2 neuron per lane), MUFU tanh,
//            u-jet to order 2, w-jet to order 4, stored pre-scaled
//            (U_k = u^(k) h^k / k!, W_k = w^(k) h^k / k!), two float4 planes.
// eval_tab:  4.2KB jet table in SMEM; 4 points/thread, float4 I/O; per point
//            TWO LDS.128, six fields via Horner in t = z*128 - rn(z*128).

#define EA_C 1.0e4f
#define EI_C 1.0e2f
#define NODES 128
#define NNODES (NODES + 1)
#define FNODES 128.0f
#define FN2 16384.0f           // NODES^2
#define FN3 2097152.0f         // NODES^3
#define TWO_LOG2E 2.8853900817779268f   // 2/ln(2)

// plane A: (U0, U1, U2, W4) ; plane B: (W0, W1, W2, W3)
__device__ float4 g_tabA[NNODES];
__device__ float4 g_tabB[NNODES];

// tanh + sech^2 via MUFU, no cancellation near saturation:
// e = e^{2a}; q = 2/(e+1); t = 1-q; s = q^2 e
__device__ __forceinline__ void tanh_pair(float a, float& t, float& s) {
    float p = a * TWO_LOG2E;
    float e;
    asm("ex2.approx.f32 %0, %1;" : "=f"(e) : "f"(p));
    float d = e + 1.0f;
    float r;
    asm("rcp.approx.f32 %0, %1;" : "=f"(r) : "f"(d));
    float q = r + r;
    t = 1.0f - q;
    s = q * q * e;
}

// ------------------------- Kernel A: build table -------------------------
// gtid/16 = node, gtid%16 = layer-2 output neuron handled by this lane.
__global__ __launch_bounds__(256) void build_tab(
    const float* __restrict__ W1, const float* __restrict__ b1,
    const float* __restrict__ W2, const float* __restrict__ b2,
    const float* __restrict__ W3, const float* __restrict__ b3)
{
    int gtid = blockIdx.x * blockDim.x + threadIdx.x;
    int grp  = gtid >> 4;
    int part = gtid & 15;
    int node = grp < NNODES ? grp : (NNODES - 1);   // clamp, keep warp uniform
    bool writer = (part == 0) && (grp < NNODES);

    const float hstep = 1.0f / FNODES;
    float z = (float)node * hstep;

    // tanh derivative chain: f1=s; f2=-2ts; f3=2s(2t^2-s); f4=8ts(2s-t^2)

    // ---- layer 1 jets (all 16 neurons per lane): h_k = f_k W1^k ----
    float h0[16], h1[16], h2[16], h3[16], h4[16];
#pragma unroll
    for (int j = 0; j < 16; j++) {
        float w  = W1[j];
        float a0 = fmaf(w, z, b1[j]);
        float t, s;
        tanh_pair(a0, t, s);
        float t2 = t * t;
        float f2 = -2.0f * t * s;
        float f3 = 2.0f * s * fmaf(2.0f, t2, -s);
        float f4 = 8.0f * t * s * fmaf(-1.0f, t2, 2.0f * s);
        float w2 = w * w;
        h0[j] = t;
        h1[j] = s * w;
        h2[j] = f2 * w2;
        h3[j] = f3 * w2 * w;
        h4[j] = f4 * w2 * w2;
    }

    // ---- layer 2 (tanh) + layer 3 fused; ONE output neuron per lane ----
    int j = part;
    float g0 = b2[j], g1 = 0.f, g2 = 0.f, g3 = 0.f, g4 = 0.f;
    const float4* w2row = reinterpret_cast<const float4*>(W2 + j * 16);
#pragma unroll
    for (int kk = 0; kk < 4; kk++) {
        float4 wv = w2row[kk];
        float wq[4] = {wv.x, wv.y, wv.z, wv.w};
#pragma unroll
        for (int m = 0; m < 4; m++) {
            int k = 4 * kk + m;
            float w = wq[m];
            g0 = fmaf(w, h0[k], g0);
            g1 = fmaf(w, h1[k], g1);
            g2 = fmaf(w, h2[k], g2);
            g3 = fmaf(w, h3[k], g3);
            g4 = fmaf(w, h4[k], g4);
        }
    }
    float t, s;
    tanh_pair(g0, t, s);
    float t2 = t * t;
    float f2 = -2.0f * t * s;
    float f3 = 2.0f * s * fmaf(2.0f, t2, -s);
    float f4 = 8.0f * t * s * fmaf(-1.0f, t2, 2.0f * s);

    // Faa di Bruno for y = tanh(g(x)):
    float g1sq = g1 * g1;
    float y1 = s * g1;
    float y2 = fmaf(s, g2, f2 * g1sq);
    float y3 = fmaf(s, g3, fmaf(3.0f * f2 * g1, g2, f3 * g1sq * g1));
    float y4 = fmaf(s, g4,
               fmaf(f2, fmaf(4.0f * g1, g3, 3.0f * g2 * g2),
               fmaf(6.0f * f3 * g1sq, g2, f4 * g1sq * g1sq)));

    float wu = W3[j];
    float ww = W3[16 + j];
    float u0 = wu * t,  u1 = wu * y1, u2 = wu * y2;
    float w0 = ww * t,  w1 = ww * y1;
    float w2a = ww * y2, w3a = ww * y3, w4a = ww * y4;

    // ---- reduce the partials across the 16 lanes of this node ----
#define RED16(v) v += __shfl_xor_sync(0xffffffffu, v, 1); \
                 v += __shfl_xor_sync(0xffffffffu, v, 2); \
                 v += __shfl_xor_sync(0xffffffffu, v, 4); \
                 v += __shfl_xor_sync(0xffffffffu, v, 8);
    RED16(u0) RED16(u1) RED16(u2)
    RED16(w0) RED16(w1) RED16(w2a) RED16(w3a) RED16(w4a)
#undef RED16

    if (writer) {
        u0 += b3[0];
        w0 += b3[1];
        const float h1f = hstep;
        const float h2f = hstep * hstep * 0.5f;
        const float h3f = hstep * hstep * hstep * (1.0f / 6.0f);
        const float h4f = hstep * hstep * hstep * hstep * (1.0f / 24.0f);
        g_tabA[node] = make_float4(u0, u1 * h1f, u2 * h2f, w4a * h4f);
        g_tabB[node] = make_float4(w0, w1 * h1f, w2a * h2f, w3a * h3f);
    }
}

// ------------------------- Kernel B: evaluate -------------------------
__device__ __forceinline__ void eval_point(
    const float4* __restrict__ sA, const float4* __restrict__ sB, float z,
    float& u, float& w, float& wx, float& Nf, float& Mf, float& Qf)
{
    float f = z * FNODES;                       // exact (power-of-2 scale)
    int idx = __float2int_rn(f);
    idx = idx < 0 ? 0 : (idx > NODES ? NODES : idx);
    float t = f - (float)idx;                   // exact, in [-1/2, 1/2]

    float4 A = sA[idx];    // (U0, U1, U2, W4)
    float4 B = sB[idx];    // (W0, W1, W2, W3)

    // u = U0 + U1 t + U2 t^2
    u  = fmaf(t, fmaf(t, A.z, A.y), A.x);
    // u' = NODES (U1 + 2U2 t)
    float up = FNODES * fmaf(t, A.z + A.z, A.y);
    // w = W0 + W1 t + W2 t^2 + W3 t^3 + W4 t^4
    w  = fmaf(t, fmaf(t, fmaf(t, fmaf(t, A.w, B.w), B.z), B.y), B.x);
    // w' = NODES (W1 + 2W2 t + 3W3 t^2 + 4W4 t^3)
    wx = FNODES * fmaf(t, fmaf(t, fmaf(t, 4.0f * A.w, 3.0f * B.w), B.z + B.z), B.y);
    // w'' = NODES^2 (2W2 + 6W3 t + 12W4 t^2)
    float wpp = FN2 * fmaf(t, fmaf(t, 12.0f * A.w, 6.0f * B.w), B.z + B.z);
    // w''' = NODES^3 (6W3 + 24W4 t)
    float wppp = FN3 * fmaf(t, 24.0f * A.w, 6.0f * B.w);

    Nf = EA_C * fmaf(0.5f * wx, wx, up);
    Mf = -EI_C * wpp;
    Qf = fmaf(Nf, wx, -EI_C * wppp);
}

__global__ __launch_bounds__(256) void eval_tab(
    const float* __restrict__ x, float* __restrict__ out, int n)
{
    __shared__ float4 sA[NNODES];   // 2,064 B
    __shared__ float4 sB[NNODES];   // 2,064 B

    int n4 = n >> 2;
    int q = blockIdx.x * blockDim.x + threadIdx.x;

    // prefetch x BEFORE the table prologue so its DRAM latency overlaps it
    float4 xs = make_float4(0.f, 0.f, 0.f, 0.f);
    bool valid = q < n4;
    const float4* x4 = reinterpret_cast<const float4*>(x);
    if (valid) xs = x4[q];

    if (threadIdx.x < NNODES) {
        sA[threadIdx.x] = g_tabA[threadIdx.x];
        sB[threadIdx.x] = g_tabB[threadIdx.x];
    }
    __syncthreads();

    if (!valid) return;

    float4 ru, rw, rwx, rN, rM, rQ;
    eval_point(sA, sB, xs.x, ru.x, rw.x, rwx.x, rN.x, rM.x, rQ.x);
    eval_point(sA, sB, xs.y, ru.y, rw.y, rwx.y, rN.y, rM.y, rQ.y);
    eval_point(sA, sB, xs.z, ru.z, rw.z, rwx.z, rN.z, rM.z, rQ.z);
    eval_point(sA, sB, xs.w, ru.w, rw.w, rwx.w, rN.w, rM.w, rQ.w);

    float4* o4 = reinterpret_cast<float4*>(out);
    o4[0 * n4 + q] = ru;
    o4[1 * n4 + q] = rw;
    o4[2 * n4 + q] = rwx;
    o4[3 * n4 + q] = rN;
    o4[4 * n4 + q] = rM;
    o4[5 * n4 + q] = rQ;
}

extern "C" void kernel_launch(void* const* d_in, const int* in_sizes, int n_in,
                              void* d_out, int out_size)
{
    const float* x  = (const float*)d_in[0];
    const float* W1 = (const float*)d_in[1];
    const float* b1 = (const float*)d_in[2];
    const float* W2 = (const float*)d_in[3];
    const float* b2 = (const float*)d_in[4];
    const float* W3 = (const float*)d_in[5];
    const float* b3 = (const float*)d_in[6];
    float* out = (float*)d_out;
    int n = in_sizes[0];

    int bthreads = 16 * NNODES;                      // 2064
    build_tab<<<(bthreads + 255) / 256, 256>>>(W1, b1, W2, b2, W3, b3);

    int n4 = n >> 2;
    int grid = (n4 + 255) / 256;                     // 512 for n = 524288
    eval_tab<<<grid, 256>>>(x, out, n);
}

// round 11
// speedup vs baseline: 1.0238x; 1.0238x over previous
#include <cuda_runtime.h>
#include <math.h>

// PINN beam fields: Taylor-jet table (129 nodes) + nearest-node Taylor eval.
// build_tab: 32 lanes per node (each lane: half the k-sum of one layer-2
//            neuron), MUFU tanh, u-jet to order 2, w-jet to order 4, stored
//            pre-scaled (U_k = u^(k) h^k/k!, W_k = w^(k) h^k/k!), 2 planes.
// eval_tab:  4.2KB jet table in SMEM; 2 points/thread, float2 I/O, 512x512;
//            per point TWO LDS.128, six fields via Horner in
//            t = z*128 - rn(z*128) in [-1/2, 1/2].

#define EA_C 1.0e4f
#define EI_C 1.0e2f
#define NODES 128
#define NNODES (NODES + 1)
#define FNODES 128.0f
#define FN2 16384.0f           // NODES^2
#define FN3 2097152.0f         // NODES^3
#define TWO_LOG2E 2.8853900817779268f   // 2/ln(2)

// plane A: (U0, U1, U2, W4) ; plane B: (W0, W1, W2, W3)
__device__ float4 g_tabA[NNODES];
__device__ float4 g_tabB[NNODES];

// tanh + sech^2 via MUFU, no cancellation near saturation:
// e = e^{2a}; q = 2/(e+1); t = 1-q; s = q^2 e
__device__ __forceinline__ void tanh_pair(float a, float& t, float& s) {
    float p = a * TWO_LOG2E;
    float e;
    asm("ex2.approx.f32 %0, %1;" : "=f"(e) : "f"(p));
    float d = e + 1.0f;
    float r;
    asm("rcp.approx.f32 %0, %1;" : "=f"(r) : "f"(d));
    float q = r + r;
    t = 1.0f - q;
    s = q * q * e;
}

// ------------------------- Kernel A: build table -------------------------
// gtid/32 = node; lane = gtid%32. neuron j = lane%16, k-half = lane/16.
// Each lane: layer-1 jets for its 8 k's, half of neuron j's k-sum.
// Reduction over all 32 lanes sums both the k-halves and the 16 neurons.
__global__ __launch_bounds__(256) void build_tab(
    const float* __restrict__ W1, const float* __restrict__ b1,
    const float* __restrict__ W2, const float* __restrict__ b2,
    const float* __restrict__ W3, const float* __restrict__ b3)
{
    int gtid = blockIdx.x * blockDim.x + threadIdx.x;
    int grp  = gtid >> 5;
    int lane = gtid & 31;
    int j    = lane & 15;            // output neuron
    int khalf = lane >> 4;           // 0: k in [0,8), 1: k in [8,16)
    int node = grp < NNODES ? grp : (NNODES - 1);   // clamp, keep warp uniform
    bool writer = (lane == 0) && (grp < NNODES);

    const float hstep = 1.0f / FNODES;
    float z = (float)node * hstep;

    // tanh derivative chain: f1=s; f2=-2ts; f3=2s(2t^2-s); f4=8ts(2s-t^2)

    // ---- layer 1 jets for this lane's 8 k's; fused partial k-sum ----
    int k0 = khalf * 8;
    float g0 = 0.f, g1 = 0.f, g2 = 0.f, g3 = 0.f, g4 = 0.f;
#pragma unroll
    for (int m = 0; m < 8; m++) {
        int k = k0 + m;
        float w1k = W1[k];
        float a0  = fmaf(w1k, z, b1[k]);
        float t, s;
        tanh_pair(a0, t, s);
        float t2 = t * t;
        float f2 = -2.0f * t * s;
        float f3 = 2.0f * s * fmaf(2.0f, t2, -s);
        float f4 = 8.0f * t * s * fmaf(-1.0f, t2, 2.0f * s);
        float wsq = w1k * w1k;

        float w = W2[j * 16 + k];
        g0 = fmaf(w, t, g0);
        g1 = fmaf(w, s * w1k, g1);
        g2 = fmaf(w, f2 * wsq, g2);
        g3 = fmaf(w, f3 * wsq * w1k, g3);
        g4 = fmaf(w, f4 * wsq * wsq, g4);
    }

    // combine the two k-halves (lanes j and j+16 hold the halves)
    g0 += __shfl_xor_sync(0xffffffffu, g0, 16);
    g1 += __shfl_xor_sync(0xffffffffu, g1, 16);
    g2 += __shfl_xor_sync(0xffffffffu, g2, 16);
    g3 += __shfl_xor_sync(0xffffffffu, g3, 16);
    g4 += __shfl_xor_sync(0xffffffffu, g4, 16);
    g0 += b2[j];

    // ---- layer 2 tanh jets + layer 3 partials (both k-half lanes compute
    //      identical values; halved by 0.5f before the full-warp reduce) ----
    float t, s;
    tanh_pair(g0, t, s);
    float t2 = t * t;
    float f2 = -2.0f * t * s;
    float f3 = 2.0f * s * fmaf(2.0f, t2, -s);
    float f4 = 8.0f * t * s * fmaf(-1.0f, t2, 2.0f * s);

    // Faa di Bruno for y = tanh(g(x)):
    float g1sq = g1 * g1;
    float y1 = s * g1;
    float y2 = fmaf(s, g2, f2 * g1sq);
    float y3 = fmaf(s, g3, fmaf(3.0f * f2 * g1, g2, f3 * g1sq * g1));
    float y4 = fmaf(s, g4,
               fmaf(f2, fmaf(4.0f * g1, g3, 3.0f * g2 * g2),
               fmaf(6.0f * f3 * g1sq, g2, f4 * g1sq * g1sq)));

    float wu = 0.5f * W3[j];        // halve: value duplicated in both k-halves
    float ww = 0.5f * W3[16 + j];
    float u0 = wu * t,  u1 = wu * y1, u2 = wu * y2;
    float w0 = ww * t,  w1 = ww * y1;
    float w2a = ww * y2, w3a = ww * y3, w4a = ww * y4;

    // ---- reduce the partials across all 32 lanes of this node ----
#define RED32(v) v += __shfl_xor_sync(0xffffffffu, v, 1); \
                 v += __shfl_xor_sync(0xffffffffu, v, 2); \
                 v += __shfl_xor_sync(0xffffffffu, v, 4); \
                 v += __shfl_xor_sync(0xffffffffu, v, 8); \
                 v += __shfl_xor_sync(0xffffffffu, v, 16);
    RED32(u0) RED32(u1) RED32(u2)
    RED32(w0) RED32(w1) RED32(w2a) RED32(w3a) RED32(w4a)
#undef RED32

    if (writer) {
        u0 += b3[0];
        w0 += b3[1];
        const float h1f = hstep;
        const float h2f = hstep * hstep * 0.5f;
        const float h3f = hstep * hstep * hstep * (1.0f / 6.0f);
        const float h4f = hstep * hstep * hstep * hstep * (1.0f / 24.0f);
        g_tabA[node] = make_float4(u0, u1 * h1f, u2 * h2f, w4a * h4f);
        g_tabB[node] = make_float4(w0, w1 * h1f, w2a * h2f, w3a * h3f);
    }
}

// ------------------------- Kernel B: evaluate -------------------------
__device__ __forceinline__ void eval_point(
    const float4* __restrict__ sA, const float4* __restrict__ sB, float z,
    float& u, float& w, float& wx, float& Nf, float& Mf, float& Qf)
{
    float f = z * FNODES;                       // exact (power-of-2 scale)
    int idx = __float2int_rn(f);
    idx = idx < 0 ? 0 : (idx > NODES ? NODES : idx);
    float t = f - (float)idx;                   // exact, in [-1/2, 1/2]

    float4 A = sA[idx];    // (U0, U1, U2, W4)
    float4 B = sB[idx];    // (W0, W1, W2, W3)

    // u = U0 + U1 t + U2 t^2
    u  = fmaf(t, fmaf(t, A.z, A.y), A.x);
    // u' = NODES (U1 + 2U2 t)
    float up = FNODES * fmaf(t, A.z + A.z, A.y);
    // w = W0 + W1 t + W2 t^2 + W3 t^3 + W4 t^4
    w  = fmaf(t, fmaf(t, fmaf(t, fmaf(t, A.w, B.w), B.z), B.y), B.x);
    // w' = NODES (W1 + 2W2 t + 3W3 t^2 + 4W4 t^3)
    wx = FNODES * fmaf(t, fmaf(t, fmaf(t, 4.0f * A.w, 3.0f * B.w), B.z + B.z), B.y);
    // w'' = NODES^2 (2W2 + 6W3 t + 12W4 t^2)
    float wpp = FN2 * fmaf(t, fmaf(t, 12.0f * A.w, 6.0f * B.w), B.z + B.z);
    // w''' = NODES^3 (6W3 + 24W4 t)
    float wppp = FN3 * fmaf(t, 24.0f * A.w, 6.0f * B.w);

    Nf = EA_C * fmaf(0.5f * wx, wx, up);
    Mf = -EI_C * wpp;
    Qf = fmaf(Nf, wx, -EI_C * wppp);
}

__global__ __launch_bounds__(512) void eval_tab(
    const float* __restrict__ x, float* __restrict__ out, int n)
{
    __shared__ float4 sA[NNODES];   // 2,064 B
    __shared__ float4 sB[NNODES];   // 2,064 B

    int n2 = n >> 1;
    int q = blockIdx.x * blockDim.x + threadIdx.x;

    // prefetch x BEFORE the table prologue so its DRAM latency overlaps it
    float2 xs = make_float2(0.f, 0.f);
    bool valid = q < n2;
    const float2* x2 = reinterpret_cast<const float2*>(x);
    if (valid) xs = x2[q];

    if (threadIdx.x < NNODES) {
        sA[threadIdx.x] = g_tabA[threadIdx.x];
        sB[threadIdx.x] = g_tabB[threadIdx.x];
    }
    __syncthreads();

    if (!valid) return;

    float2 ru, rw, rwx, rN, rM, rQ;
    eval_point(sA, sB, xs.x, ru.x, rw.x, rwx.x, rN.x, rM.x, rQ.x);
    eval_point(sA, sB, xs.y, ru.y, rw.y, rwx.y, rN.y, rM.y, rQ.y);

    float2* o2 = reinterpret_cast<float2*>(out);
    o2[0 * n2 + q] = ru;
    o2[1 * n2 + q] = rw;
    o2[2 * n2 + q] = rwx;
    o2[3 * n2 + q] = rN;
    o2[4 * n2 + q] = rM;
    o2[5 * n2 + q] = rQ;
}

extern "C" void kernel_launch(void* const* d_in, const int* in_sizes, int n_in,
                              void* d_out, int out_size)
{
    const float* x  = (const float*)d_in[0];
    const float* W1 = (const float*)d_in[1];
    const float* b1 = (const float*)d_in[2];
    const float* W2 = (const float*)d_in[3];
    const float* b2 = (const float*)d_in[4];
    const float* W3 = (const float*)d_in[5];
    const float* b3 = (const float*)d_in[6];
    float* out = (float*)d_out;
    int n = in_sizes[0];

    int bthreads = 32 * NNODES;                      // 4128
    build_tab<<<(bthreads + 255) / 256, 256>>>(W1, b1, W2, b2, W3, b3);

    int n2 = n >> 1;
    int grid = (n2 + 511) / 512;                     // 512 for n = 524288
    eval_tab<<<grid, 512>>>(x, out, n);
}